// round 15
// baseline (speedup 1.0000x reference)
#include <cuda_runtime.h>

#define D 128
#define N_ING 100000
#define N_TASTE 50000
#define E_EDGES 600000
#define NEG_SLOPE 0.2f
#define CAP 64          // per-dst bucket capacity; deg ~ Poisson(12), P(>64) < 1e-20

// ---------------- scratch (device globals) ----------------
__device__ float  g_v_src[D];
__device__ float  g_v_dst[D];
__device__ float  g_c_src, g_c_dst;
__device__ float  g_a_src[N_ING];
__device__ float  g_a_dst[N_TASTE];
__device__ int    g_cnt[N_TASTE];                  // degree cursor / epilogue mask
__device__ int2   g_slot[(size_t)N_TASTE * CAP];   // (src, exp-weight bits)
__device__ float2 g_wpk[D * D];                    // W packed (hi, lo) tf32 parts
__device__ float  g_gbuf[(size_t)N_TASTE * D];     // aggregated rows (25.6MB)

// ---------------- tf32 helpers ----------------
__device__ __forceinline__ void split_tf32(float x, unsigned& hi, unsigned& lo) {
    asm("cvt.rna.tf32.f32 %0, %1;" : "=r"(hi) : "f"(x));
    float lof = x - __uint_as_float(hi);
    asm("cvt.rna.tf32.f32 %0, %1;" : "=r"(lo) : "f"(lof));
}
__device__ __forceinline__ void mma_tf32(float* c,
                                         unsigned a0, unsigned a1, unsigned a2, unsigned a3,
                                         unsigned b0, unsigned b1) {
    asm volatile("mma.sync.aligned.m16n8k8.row.col.f32.tf32.tf32.f32 "
                 "{%0,%1,%2,%3}, {%4,%5,%6,%7}, {%8,%9}, {%0,%1,%2,%3};"
                 : "+f"(c[0]), "+f"(c[1]), "+f"(c[2]), "+f"(c[3])
                 : "r"(a0), "r"(a1), "r"(a2), "r"(a3), "r"(b0), "r"(b1));
}

// ---------------- K1: prep = (v vectors + bias dots) ∪ splitW --------------
__global__ void k_prep(const float* __restrict__ W_ing,  const float* __restrict__ b_ing,
                       const float* __restrict__ W_taste,const float* __restrict__ b_taste,
                       const float* __restrict__ att_src,const float* __restrict__ att_dst) {
    if (blockIdx.x < 33) {
        int w    = (blockIdx.x * blockDim.x + threadIdx.x) >> 5;
        int lane = threadIdx.x & 31;
        if (w >= 258) return;
        const float* vecA;
        const float* vecB;
        if (w < 128)      { vecA = W_ing   + w * D;         vecB = att_src; }
        else if (w < 256) { vecA = W_taste + (w - 128) * D; vecB = att_dst; }
        else if (w == 256){ vecA = b_ing;                   vecB = att_src; }
        else              { vecA = b_taste;                 vecB = att_dst; }
        float4 a = ((const float4*)vecA)[lane];
        float4 c = ((const float4*)vecB)[lane];
        float s = a.x * c.x + a.y * c.y + a.z * c.z + a.w * c.w;
        #pragma unroll
        for (int o = 16; o; o >>= 1) s += __shfl_down_sync(0xffffffffu, s, o);
        if (lane == 0) {
            if (w < 128)       g_v_src[w] = s;
            else if (w < 256)  g_v_dst[w - 128] = s;
            else if (w == 256) g_c_src = s;
            else               g_c_dst = s;
        }
    } else {
        int i = (blockIdx.x - 33) * 256 + threadIdx.x;  // 64 blocks cover 16384
        if (i >= D * D) return;
        unsigned hi, lo;
        split_tf32(W_ing[i], hi, lo);
        g_wpk[i] = make_float2(__uint_as_float(hi), __uint_as_float(lo));
    }
}

// ---------------- K2: parallel bundle -------------------------------------
// blocks [0,3125):      out_ing copy + a_src (x_ing read once, 4 rows/warp)
// blocks [3125,4688):   a_dst (4 rows/warp)
// blocks [4688,4737):   zero g_cnt
#define PAR_ADST0 3125
#define PAR_ZERO0 4688
#define PAR_GRID  4737
__global__ void k_par(const float* __restrict__ x_ing, const float* __restrict__ x_taste,
                      float* __restrict__ out_ing) {
    int b = blockIdx.x;
    int lane = threadIdx.x & 31;
    int wrp  = threadIdx.x >> 5;
    if (b < PAR_ADST0) {
        int w = b * 8 + wrp;
        int row0 = w * 4;                          // exact: 25000 warps * 4 = 100000
        const float4* x4 = (const float4*)x_ing;
        float4* o4 = (float4*)out_ing;
        float4 vv = ((const float4*)g_v_src)[lane];
        float  cc = g_c_src;
        float4 xv[4];
        #pragma unroll
        for (int r = 0; r < 4; r++) xv[r] = x4[(size_t)(row0 + r) * 32 + lane];
        #pragma unroll
        for (int r = 0; r < 4; r++) {
            o4[(size_t)(row0 + r) * 32 + lane] = xv[r];
            float s = xv[r].x * vv.x + xv[r].y * vv.y + xv[r].z * vv.z + xv[r].w * vv.w;
            #pragma unroll
            for (int o = 16; o; o >>= 1) s += __shfl_down_sync(0xffffffffu, s, o);
            if (lane == 0) g_a_src[row0 + r] = s + cc;
        }
    } else if (b < PAR_ZERO0) {
        int w = (b - PAR_ADST0) * 8 + wrp;
        int row0 = w * 4;
        if (row0 >= N_TASTE) return;
        const float4* x4 = (const float4*)x_taste;
        float4 vv = ((const float4*)g_v_dst)[lane];
        float  cc = g_c_dst;
        float4 xv[4];
        #pragma unroll
        for (int r = 0; r < 4; r++) xv[r] = x4[(size_t)(row0 + r) * 32 + lane];
        #pragma unroll
        for (int r = 0; r < 4; r++) {
            float s = xv[r].x * vv.x + xv[r].y * vv.y + xv[r].z * vv.z + xv[r].w * vv.w;
            #pragma unroll
            for (int o = 16; o; o >>= 1) s += __shfl_down_sync(0xffffffffu, s, o);
            if (lane == 0) g_a_dst[row0 + r] = s + cc;
        }
    } else {
        for (int i = (b - PAR_ZERO0) * 256 + threadIdx.x; i < N_TASTE; i += 49 * 256)
            g_cnt[i] = 0;
    }
}

// ---------------- K3: fill buckets; 2 edges/thread (int2 loads, MLP x2) ----
__global__ void k_fill(const int2* __restrict__ src2, const int2* __restrict__ dst2) {
    int i = blockIdx.x * blockDim.x + threadIdx.x;
    if (i >= E_EDGES / 2) return;
    int2 s2 = src2[i];
    int2 t2 = dst2[i];
    float l0 = g_a_src[s2.x] + g_a_dst[t2.x];
    float l1 = g_a_src[s2.y] + g_a_dst[t2.y];
    l0 = l0 > 0.f ? l0 : NEG_SLOPE * l0;
    l1 = l1 > 0.f ? l1 : NEG_SLOPE * l1;
    int p0 = atomicAdd(&g_cnt[t2.x], 1);        // pos < CAP w.h.p. (Poisson tail)
    g_slot[(size_t)t2.x * CAP + p0] = make_int2(s2.x, __float_as_int(__expf(l0)));
    int p1 = atomicAdd(&g_cnt[t2.y], 1);
    g_slot[(size_t)t2.y * CAP + p1] = make_int2(s2.y, __float_as_int(__expf(l1)));
}

// ---------------- K4: agg; 2 warps per dst (half-row each), high occ -------
// 100000 warps = 12500 blocks; warp gw: dst = gw>>1, column half = gw&1.
__global__ void __launch_bounds__(256, 8) k_agg(const float* __restrict__ x_ing) {
    int lane = threadIdx.x & 31;
    int gw   = blockIdx.x * 8 + (threadIdx.x >> 5);
    int t    = gw >> 1;
    int half = gw & 1;
    int coff = half * 32 + lane;                 // float2 column index within row
    int n = g_cnt[t];
    const int2* sp = g_slot + (size_t)t * CAP;
    const float2* x2 = (const float2*)x_ing;     // row = 64 float2
    float2 acc = make_float2(0.f, 0.f);
    float wsum = 0.f;
    int e = 0;
    for (; e + 4 <= n; e += 4) {
        int2 e0 = sp[e], e1 = sp[e+1], e2 = sp[e+2], e3 = sp[e+3];
        float w0 = __int_as_float(e0.y), w1 = __int_as_float(e1.y);
        float w2 = __int_as_float(e2.y), w3 = __int_as_float(e3.y);
        float2 v0 = x2[(size_t)e0.x * 64 + coff];
        float2 v1 = x2[(size_t)e1.x * 64 + coff];
        float2 v2 = x2[(size_t)e2.x * 64 + coff];
        float2 v3 = x2[(size_t)e3.x * 64 + coff];
        wsum  += w0 + w1 + w2 + w3;
        acc.x += w0*v0.x + w1*v1.x + w2*v2.x + w3*v3.x;
        acc.y += w0*v0.y + w1*v1.y + w2*v2.y + w3*v3.y;
    }
    for (; e < n; e++) {
        int2 ee = sp[e];
        float w = __int_as_float(ee.y);
        float2 v = x2[(size_t)ee.x * 64 + coff];
        wsum += w;
        acc.x += w*v.x; acc.y += w*v.y;
    }
    float inv = 1.f / (wsum + 1e-16f);
    acc.x *= inv; acc.y *= inv;
    ((float2*)g_gbuf)[(size_t)t * 64 + coff] = acc;
}

// ---------------- K5: TF32 3-pass MMA, packed W(hi,lo) in smem --------------
#define TM 128
#define SROW 132
__global__ void __launch_bounds__(256) k_gemm(const float* __restrict__ bias,
                                              const float* __restrict__ x_taste,
                                              float* __restrict__ out_taste) {
    extern __shared__ float2 wpk[];     // [128][SROW] packed (hi,lo)
    int tid  = threadIdx.x;
    int lane = tid & 31;
    int wrp  = tid >> 5;
    int row0 = blockIdx.x * TM;

    for (int i = tid; i < D * D; i += 256) {
        int k = i >> 7, n = i & 127;
        wpk[k * SROW + n] = g_wpk[i];
    }
    __syncthreads();

    int g = lane >> 2, t4 = lane & 3;
    int rbase = wrp * 16;
    int r0 = row0 + rbase + g;
    int r1 = r0 + 8;
    bool v0 = r0 < N_TASTE, v1 = r1 < N_TASTE;
    const float* A0 = g_gbuf + (size_t)(v0 ? r0 : 0) * D;
    const float* A1 = g_gbuf + (size_t)(v1 ? r1 : 0) * D;

    float acc[16][4];
    #pragma unroll
    for (int nn = 0; nn < 16; nn++)
        #pragma unroll
        for (int j = 0; j < 4; j++) acc[nn][j] = 0.f;

    #pragma unroll 1
    for (int kk = 0; kk < 16; kk++) {
        int k0 = kk * 8;
        float a0f = v0 ? A0[k0 + t4    ] : 0.f;
        float a2f = v0 ? A0[k0 + t4 + 4] : 0.f;
        float a1f = v1 ? A1[k0 + t4    ] : 0.f;
        float a3f = v1 ? A1[k0 + t4 + 4] : 0.f;
        unsigned a0h,a0l,a1h,a1l,a2h,a2l,a3h,a3l;
        split_tf32(a0f, a0h, a0l);
        split_tf32(a1f, a1h, a1l);
        split_tf32(a2f, a2h, a2l);
        split_tf32(a3f, a3h, a3l);
        #pragma unroll
        for (int nn = 0; nn < 16; nn++) {
            int col = nn * 8 + g;
            float2 b0 = wpk[(k0 + t4    ) * SROW + col];   // LDS.64: (hi, lo)
            float2 b1 = wpk[(k0 + t4 + 4) * SROW + col];
            unsigned b0h = __float_as_uint(b0.x), b0l = __float_as_uint(b0.y);
            unsigned b1h = __float_as_uint(b1.x), b1l = __float_as_uint(b1.y);
            mma_tf32(acc[nn], a0h,a1h,a2h,a3h, b0h,b1h);   // hi*hi
            mma_tf32(acc[nn], a0h,a1h,a2h,a3h, b0l,b1l);   // hi*lo
            mma_tf32(acc[nn], a0l,a1l,a2l,a3l, b0h,b1h);   // lo*hi
        }
    }

    float has0 = (v0 && g_cnt[r0] > 0) ? 1.f : 0.f;
    float has1 = (v1 && g_cnt[r1] > 0) ? 1.f : 0.f;
    #pragma unroll
    for (int nn = 0; nn < 16; nn++) {
        int col = nn * 8 + 2 * t4;
        float2 bj = *(const float2*)(bias + col);
        if (v0) {
            float2 xt = *(const float2*)(x_taste + (size_t)r0 * D + col);
            float2 o;
            o.x = fmaxf(has0 * (acc[nn][0] + bj.x), 0.f) * 0.5f + 0.5f * xt.x;
            o.y = fmaxf(has0 * (acc[nn][1] + bj.y), 0.f) * 0.5f + 0.5f * xt.y;
            *(float2*)(out_taste + (size_t)r0 * D + col) = o;
        }
        if (v1) {
            float2 xt = *(const float2*)(x_taste + (size_t)r1 * D + col);
            float2 o;
            o.x = fmaxf(has1 * (acc[nn][2] + bj.x), 0.f) * 0.5f + 0.5f * xt.x;
            o.y = fmaxf(has1 * (acc[nn][3] + bj.y), 0.f) * 0.5f + 0.5f * xt.y;
            *(float2*)(out_taste + (size_t)r1 * D + col) = o;
        }
    }
}

// ---------------- launcher: single stream, 5 kernels, 0 events -------------
extern "C" void kernel_launch(void* const* d_in, const int* in_sizes, int n_in,
                              void* d_out, int out_size) {
    const float* x_ing   = (const float*)d_in[0];
    const float* x_taste = (const float*)d_in[1];
    const float* W_ing   = (const float*)d_in[2];
    const float* b_ing   = (const float*)d_in[3];
    const float* W_taste = (const float*)d_in[4];
    const float* b_taste = (const float*)d_in[5];
    const float* att_src = (const float*)d_in[6];
    const float* att_dst = (const float*)d_in[7];
    // d_in[8..10] (Wk, bk, q): softmax over single metapath == 1.0 -> dead code
    const int* src_idx = (const int*)d_in[11];
    const int* dst_idx = (const int*)d_in[12];

    float* out       = (float*)d_out;
    float* out_ing   = out;                      // [N_ING, D] == x_ing
    float* out_taste = out + (size_t)N_ING * D;  // [N_TASTE, D]

    static const int SMEM_GEMM = D * SROW * (int)sizeof(float2);  // 135168
    static bool init = false;
    if (!init) {
        init = true;
        cudaFuncSetAttribute(k_gemm, cudaFuncAttributeMaxDynamicSharedMemorySize, SMEM_GEMM);
    }

    k_prep<<<97, 256>>>(W_ing, b_ing, W_taste, b_taste, att_src, att_dst);
    k_par<<<PAR_GRID, 256>>>(x_ing, x_taste, out_ing);
    k_fill<<<(E_EDGES / 2 + 255) / 256, 256>>>((const int2*)src_idx, (const int2*)dst_idx);
    k_agg<<<12500, 256>>>(x_ing);                // 2 warps per dst
    k_gemm<<<(N_TASTE + TM - 1) / TM, 256, SMEM_GEMM>>>(b_ing, x_taste, out_taste);
}

// round 16
// speedup vs baseline: 1.0027x; 1.0027x over previous
#include <cuda_runtime.h>
#include <cuda_fp16.h>

#define D 128
#define N_ING 100000
#define N_TASTE 50000
#define E_EDGES 600000
#define NEG_SLOPE 0.2f
#define CAP 64          // per-dst bucket capacity; deg ~ Poisson(12), P(>64) < 1e-20

// ---------------- scratch (device globals) ----------------
__device__ float  g_v_src[D];
__device__ float  g_v_dst[D];
__device__ float  g_c_src, g_c_dst;
__device__ float  g_a_src[N_ING];
__device__ float  g_a_dst[N_TASTE];
__device__ int    g_cnt[N_TASTE];                  // degree cursor / epilogue mask
__device__ int2   g_slot[(size_t)N_TASTE * CAP];   // (src, exp-weight bits)
__device__ float2 g_wpk[D * D];                    // W packed (hi, lo) tf32 parts
__device__ float  g_gbuf[(size_t)N_TASTE * D];     // aggregated rows (25.6MB, fp32)
__device__ uint2  g_xh[(size_t)N_ING * 32];        // fp16 mirror of x_ing (25.6MB)

// ---------------- tf32 helpers ----------------
__device__ __forceinline__ void split_tf32(float x, unsigned& hi, unsigned& lo) {
    asm("cvt.rna.tf32.f32 %0, %1;" : "=r"(hi) : "f"(x));
    float lof = x - __uint_as_float(hi);
    asm("cvt.rna.tf32.f32 %0, %1;" : "=r"(lo) : "f"(lof));
}
__device__ __forceinline__ void mma_tf32(float* c,
                                         unsigned a0, unsigned a1, unsigned a2, unsigned a3,
                                         unsigned b0, unsigned b1) {
    asm volatile("mma.sync.aligned.m16n8k8.row.col.f32.tf32.tf32.f32 "
                 "{%0,%1,%2,%3}, {%4,%5,%6,%7}, {%8,%9}, {%0,%1,%2,%3};"
                 : "+f"(c[0]), "+f"(c[1]), "+f"(c[2]), "+f"(c[3])
                 : "r"(a0), "r"(a1), "r"(a2), "r"(a3), "r"(b0), "r"(b1));
}

// ---------------- K1: prep = (v vectors + bias dots) ∪ splitW --------------
__global__ void k_prep(const float* __restrict__ W_ing,  const float* __restrict__ b_ing,
                       const float* __restrict__ W_taste,const float* __restrict__ b_taste,
                       const float* __restrict__ att_src,const float* __restrict__ att_dst) {
    if (blockIdx.x < 33) {
        int w    = (blockIdx.x * blockDim.x + threadIdx.x) >> 5;
        int lane = threadIdx.x & 31;
        if (w >= 258) return;
        const float* vecA;
        const float* vecB;
        if (w < 128)      { vecA = W_ing   + w * D;         vecB = att_src; }
        else if (w < 256) { vecA = W_taste + (w - 128) * D; vecB = att_dst; }
        else if (w == 256){ vecA = b_ing;                   vecB = att_src; }
        else              { vecA = b_taste;                 vecB = att_dst; }
        float4 a = ((const float4*)vecA)[lane];
        float4 c = ((const float4*)vecB)[lane];
        float s = a.x * c.x + a.y * c.y + a.z * c.z + a.w * c.w;
        #pragma unroll
        for (int o = 16; o; o >>= 1) s += __shfl_down_sync(0xffffffffu, s, o);
        if (lane == 0) {
            if (w < 128)       g_v_src[w] = s;
            else if (w < 256)  g_v_dst[w - 128] = s;
            else if (w == 256) g_c_src = s;
            else               g_c_dst = s;
        }
    } else {
        int i = (blockIdx.x - 33) * 256 + threadIdx.x;  // 64 blocks cover 16384
        if (i >= D * D) return;
        unsigned hi, lo;
        split_tf32(W_ing[i], hi, lo);
        g_wpk[i] = make_float2(__uint_as_float(hi), __uint_as_float(lo));
    }
}

// ---------------- K2: parallel bundle -------------------------------------
// blocks [0,3125):      out_ing copy + fp16 mirror + a_src (x_ing read once)
// blocks [3125,4688):   a_dst (4 rows/warp)
// blocks [4688,4737):   zero g_cnt
#define PAR_ADST0 3125
#define PAR_ZERO0 4688
#define PAR_GRID  4737
__global__ void k_par(const float* __restrict__ x_ing, const float* __restrict__ x_taste,
                      float* __restrict__ out_ing) {
    int b = blockIdx.x;
    int lane = threadIdx.x & 31;
    int wrp  = threadIdx.x >> 5;
    if (b < PAR_ADST0) {
        int w = b * 8 + wrp;
        int row0 = w * 4;                          // exact: 25000 warps * 4 = 100000
        const float4* x4 = (const float4*)x_ing;
        float4* o4 = (float4*)out_ing;
        float4 vv = ((const float4*)g_v_src)[lane];
        float  cc = g_c_src;
        float4 xv[4];
        #pragma unroll
        for (int r = 0; r < 4; r++) xv[r] = x4[(size_t)(row0 + r) * 32 + lane];
        #pragma unroll
        for (int r = 0; r < 4; r++) {
            o4[(size_t)(row0 + r) * 32 + lane] = xv[r];
            // fp16 mirror: 4 floats -> 2 half2 -> uint2
            half2 h0 = __floats2half2_rn(xv[r].x, xv[r].y);
            half2 h1 = __floats2half2_rn(xv[r].z, xv[r].w);
            uint2 hp;
            hp.x = *(unsigned*)&h0;
            hp.y = *(unsigned*)&h1;
            g_xh[(size_t)(row0 + r) * 32 + lane] = hp;
            float s = xv[r].x * vv.x + xv[r].y * vv.y + xv[r].z * vv.z + xv[r].w * vv.w;
            #pragma unroll
            for (int o = 16; o; o >>= 1) s += __shfl_down_sync(0xffffffffu, s, o);
            if (lane == 0) g_a_src[row0 + r] = s + cc;
        }
    } else if (b < PAR_ZERO0) {
        int w = (b - PAR_ADST0) * 8 + wrp;
        int row0 = w * 4;
        if (row0 >= N_TASTE) return;
        const float4* x4 = (const float4*)x_taste;
        float4 vv = ((const float4*)g_v_dst)[lane];
        float  cc = g_c_dst;
        float4 xv[4];
        #pragma unroll
        for (int r = 0; r < 4; r++) xv[r] = x4[(size_t)(row0 + r) * 32 + lane];
        #pragma unroll
        for (int r = 0; r < 4; r++) {
            float s = xv[r].x * vv.x + xv[r].y * vv.y + xv[r].z * vv.z + xv[r].w * vv.w;
            #pragma unroll
            for (int o = 16; o; o >>= 1) s += __shfl_down_sync(0xffffffffu, s, o);
            if (lane == 0) g_a_dst[row0 + r] = s + cc;
        }
    } else {
        for (int i = (b - PAR_ZERO0) * 256 + threadIdx.x; i < N_TASTE; i += 49 * 256)
            g_cnt[i] = 0;
    }
}

// ---------------- K3: fill buckets with (src, exp-weight) ------------------
__global__ void k_fill(const int* __restrict__ src, const int* __restrict__ dst) {
    int e = blockIdx.x * blockDim.x + threadIdx.x;
    if (e >= E_EDGES) return;
    int si = src[e];
    int t  = dst[e];
    float l = g_a_src[si] + g_a_dst[t];
    l = l > 0.f ? l : NEG_SLOPE * l;
    int pos = atomicAdd(&g_cnt[t], 1);          // pos < CAP w.h.p. (Poisson tail)
    g_slot[(size_t)t * CAP + pos] = make_int2(si, __float_as_int(__expf(l)));
}

// ---------------- K4: agg (R13 structure, fp16 gathers: half the L2 bytes) -
__global__ void __launch_bounds__(256) k_agg() {
    int gw    = (blockIdx.x * blockDim.x + threadIdx.x) >> 5;
    int lane  = threadIdx.x & 31;
    int nwarp = (gridDim.x * blockDim.x) >> 5;
    for (int t = gw; t < N_TASTE; t += nwarp) {
        int n = g_cnt[t];
        const int2* sp = g_slot + (size_t)t * CAP;
        float4 acc = make_float4(0.f, 0.f, 0.f, 0.f);
        float wsum = 0.f;
        int e = 0;
        for (; e + 4 <= n; e += 4) {
            int2 e0 = sp[e], e1 = sp[e+1], e2 = sp[e+2], e3 = sp[e+3];
            float w0 = __int_as_float(e0.y), w1 = __int_as_float(e1.y);
            float w2 = __int_as_float(e2.y), w3 = __int_as_float(e3.y);
            uint2 p0 = g_xh[(size_t)e0.x * 32 + lane];
            uint2 p1 = g_xh[(size_t)e1.x * 32 + lane];
            uint2 p2 = g_xh[(size_t)e2.x * 32 + lane];
            uint2 p3 = g_xh[(size_t)e3.x * 32 + lane];
            wsum += w0 + w1 + w2 + w3;
            float2 a0 = __half22float2(*(half2*)&p0.x), b0 = __half22float2(*(half2*)&p0.y);
            float2 a1 = __half22float2(*(half2*)&p1.x), b1 = __half22float2(*(half2*)&p1.y);
            float2 a2 = __half22float2(*(half2*)&p2.x), b2 = __half22float2(*(half2*)&p2.y);
            float2 a3 = __half22float2(*(half2*)&p3.x), b3 = __half22float2(*(half2*)&p3.y);
            acc.x += w0*a0.x + w1*a1.x + w2*a2.x + w3*a3.x;
            acc.y += w0*a0.y + w1*a1.y + w2*a2.y + w3*a3.y;
            acc.z += w0*b0.x + w1*b1.x + w2*b2.x + w3*b3.x;
            acc.w += w0*b0.y + w1*b1.y + w2*b2.y + w3*b3.y;
        }
        for (; e < n; e++) {
            int2 ee = sp[e];
            float w = __int_as_float(ee.y);
            uint2 p = g_xh[(size_t)ee.x * 32 + lane];
            float2 a = __half22float2(*(half2*)&p.x);
            float2 bq = __half22float2(*(half2*)&p.y);
            wsum += w;
            acc.x += w*a.x; acc.y += w*a.y; acc.z += w*bq.x; acc.w += w*bq.y;
        }
        float inv = 1.f / (wsum + 1e-16f);
        acc.x *= inv; acc.y *= inv; acc.z *= inv; acc.w *= inv;
        ((float4*)g_gbuf)[(size_t)t * 32 + lane] = acc;
    }
}

// ---------------- K5: TF32 3-pass MMA, packed W(hi,lo) in smem --------------
#define TM 128
#define SROW 132
__global__ void __launch_bounds__(256) k_gemm(const float* __restrict__ bias,
                                              const float* __restrict__ x_taste,
                                              float* __restrict__ out_taste) {
    extern __shared__ float2 wpk[];     // [128][SROW] packed (hi,lo)
    int tid  = threadIdx.x;
    int lane = tid & 31;
    int wrp  = tid >> 5;
    int row0 = blockIdx.x * TM;

    for (int i = tid; i < D * D; i += 256) {
        int k = i >> 7, n = i & 127;
        wpk[k * SROW + n] = g_wpk[i];
    }
    __syncthreads();

    int g = lane >> 2, t4 = lane & 3;
    int rbase = wrp * 16;
    int r0 = row0 + rbase + g;
    int r1 = r0 + 8;
    bool v0 = r0 < N_TASTE, v1 = r1 < N_TASTE;
    const float* A0 = g_gbuf + (size_t)(v0 ? r0 : 0) * D;
    const float* A1 = g_gbuf + (size_t)(v1 ? r1 : 0) * D;

    float acc[16][4];
    #pragma unroll
    for (int nn = 0; nn < 16; nn++)
        #pragma unroll
        for (int j = 0; j < 4; j++) acc[nn][j] = 0.f;

    #pragma unroll 1
    for (int kk = 0; kk < 16; kk++) {
        int k0 = kk * 8;
        float a0f = v0 ? A0[k0 + t4    ] : 0.f;
        float a2f = v0 ? A0[k0 + t4 + 4] : 0.f;
        float a1f = v1 ? A1[k0 + t4    ] : 0.f;
        float a3f = v1 ? A1[k0 + t4 + 4] : 0.f;
        unsigned a0h,a0l,a1h,a1l,a2h,a2l,a3h,a3l;
        split_tf32(a0f, a0h, a0l);
        split_tf32(a1f, a1h, a1l);
        split_tf32(a2f, a2h, a2l);
        split_tf32(a3f, a3h, a3l);
        #pragma unroll
        for (int nn = 0; nn < 16; nn++) {
            int col = nn * 8 + g;
            float2 b0 = wpk[(k0 + t4    ) * SROW + col];   // LDS.64: (hi, lo)
            float2 b1 = wpk[(k0 + t4 + 4) * SROW + col];
            unsigned b0h = __float_as_uint(b0.x), b0l = __float_as_uint(b0.y);
            unsigned b1h = __float_as_uint(b1.x), b1l = __float_as_uint(b1.y);
            mma_tf32(acc[nn], a0h,a1h,a2h,a3h, b0h,b1h);   // hi*hi
            mma_tf32(acc[nn], a0h,a1h,a2h,a3h, b0l,b1l);   // hi*lo
            mma_tf32(acc[nn], a0l,a1l,a2l,a3l, b0h,b1h);   // lo*hi
        }
    }

    float has0 = (v0 && g_cnt[r0] > 0) ? 1.f : 0.f;
    float has1 = (v1 && g_cnt[r1] > 0) ? 1.f : 0.f;
    #pragma unroll
    for (int nn = 0; nn < 16; nn++) {
        int col = nn * 8 + 2 * t4;
        float2 bj = *(const float2*)(bias + col);
        if (v0) {
            float2 xt = *(const float2*)(x_taste + (size_t)r0 * D + col);
            float2 o;
            o.x = fmaxf(has0 * (acc[nn][0] + bj.x), 0.f) * 0.5f + 0.5f * xt.x;
            o.y = fmaxf(has0 * (acc[nn][1] + bj.y), 0.f) * 0.5f + 0.5f * xt.y;
            *(float2*)(out_taste + (size_t)r0 * D + col) = o;
        }
        if (v1) {
            float2 xt = *(const float2*)(x_taste + (size_t)r1 * D + col);
            float2 o;
            o.x = fmaxf(has1 * (acc[nn][2] + bj.x), 0.f) * 0.5f + 0.5f * xt.x;
            o.y = fmaxf(has1 * (acc[nn][3] + bj.y), 0.f) * 0.5f + 0.5f * xt.y;
            *(float2*)(out_taste + (size_t)r1 * D + col) = o;
        }
    }
}

// ---------------- launcher: single stream, 5 kernels, 0 events -------------
extern "C" void kernel_launch(void* const* d_in, const int* in_sizes, int n_in,
                              void* d_out, int out_size) {
    const float* x_ing   = (const float*)d_in[0];
    const float* x_taste = (const float*)d_in[1];
    const float* W_ing   = (const float*)d_in[2];
    const float* b_ing   = (const float*)d_in[3];
    const float* W_taste = (const float*)d_in[4];
    const float* b_taste = (const float*)d_in[5];
    const float* att_src = (const float*)d_in[6];
    const float* att_dst = (const float*)d_in[7];
    // d_in[8..10] (Wk, bk, q): softmax over single metapath == 1.0 -> dead code
    const int* src_idx = (const int*)d_in[11];
    const int* dst_idx = (const int*)d_in[12];

    float* out       = (float*)d_out;
    float* out_ing   = out;                      // [N_ING, D] == x_ing
    float* out_taste = out + (size_t)N_ING * D;  // [N_TASTE, D]

    static const int SMEM_GEMM = D * SROW * (int)sizeof(float2);  // 135168
    static bool init = false;
    if (!init) {
        init = true;
        cudaFuncSetAttribute(k_gemm, cudaFuncAttributeMaxDynamicSharedMemorySize, SMEM_GEMM);
    }

    k_prep<<<97, 256>>>(W_ing, b_ing, W_taste, b_taste, att_src, att_dst);
    k_par<<<PAR_GRID, 256>>>(x_ing, x_taste, out_ing);
    k_fill<<<(E_EDGES + 255) / 256, 256>>>(src_idx, dst_idx);
    k_agg<<<6250, 256>>>();
    k_gemm<<<(N_TASTE + TM - 1) / TM, 256, SMEM_GEMM>>>(b_ing, x_taste, out_taste);
}

// round 17
// speedup vs baseline: 1.0397x; 1.0369x over previous
#include <cuda_runtime.h>

#define D 128
#define N_ING 100000
#define N_TASTE 50000
#define E_EDGES 600000
#define NEG_SLOPE 0.2f
#define CAP 64          // per-dst bucket capacity; deg ~ Poisson(12), P(>64) < 1e-20

// ---------------- scratch (device globals) ----------------
__device__ float  g_v_src[D];
__device__ float  g_v_dst[D];
__device__ float  g_c_src, g_c_dst;
__device__ float  g_a_src[N_ING];
__device__ float  g_a_dst[N_TASTE];
__device__ int    g_cnt[N_TASTE];                  // degree cursor / epilogue mask
__device__ int2   g_slot[(size_t)N_TASTE * CAP];   // (src, exp-weight bits)
__device__ float2 g_wpk[D * D];                    // W packed (hi, lo) tf32 parts
__device__ float  g_gbuf[(size_t)N_TASTE * D];     // aggregated rows (25.6MB)

// ---------------- tf32 helpers ----------------
__device__ __forceinline__ void split_tf32(float x, unsigned& hi, unsigned& lo) {
    asm("cvt.rna.tf32.f32 %0, %1;" : "=r"(hi) : "f"(x));
    float lof = x - __uint_as_float(hi);
    asm("cvt.rna.tf32.f32 %0, %1;" : "=r"(lo) : "f"(lof));
}
__device__ __forceinline__ void mma_tf32(float* c,
                                         unsigned a0, unsigned a1, unsigned a2, unsigned a3,
                                         unsigned b0, unsigned b1) {
    asm volatile("mma.sync.aligned.m16n8k8.row.col.f32.tf32.tf32.f32 "
                 "{%0,%1,%2,%3}, {%4,%5,%6,%7}, {%8,%9}, {%0,%1,%2,%3};"
                 : "+f"(c[0]), "+f"(c[1]), "+f"(c[2]), "+f"(c[3])
                 : "r"(a0), "r"(a1), "r"(a2), "r"(a3), "r"(b0), "r"(b1));
}

// ---------------- K1: prep = (v vectors + bias dots) ∪ splitW --------------
__global__ void k_prep(const float* __restrict__ W_ing,  const float* __restrict__ b_ing,
                       const float* __restrict__ W_taste,const float* __restrict__ b_taste,
                       const float* __restrict__ att_src,const float* __restrict__ att_dst) {
    if (blockIdx.x < 33) {
        int w    = (blockIdx.x * blockDim.x + threadIdx.x) >> 5;
        int lane = threadIdx.x & 31;
        if (w >= 258) return;
        const float* vecA;
        const float* vecB;
        if (w < 128)      { vecA = W_ing   + w * D;         vecB = att_src; }
        else if (w < 256) { vecA = W_taste + (w - 128) * D; vecB = att_dst; }
        else if (w == 256){ vecA = b_ing;                   vecB = att_src; }
        else              { vecA = b_taste;                 vecB = att_dst; }
        float4 a = ((const float4*)vecA)[lane];
        float4 c = ((const float4*)vecB)[lane];
        float s = a.x * c.x + a.y * c.y + a.z * c.z + a.w * c.w;
        #pragma unroll
        for (int o = 16; o; o >>= 1) s += __shfl_down_sync(0xffffffffu, s, o);
        if (lane == 0) {
            if (w < 128)       g_v_src[w] = s;
            else if (w < 256)  g_v_dst[w - 128] = s;
            else if (w == 256) g_c_src = s;
            else               g_c_dst = s;
        }
    } else {
        int i = (blockIdx.x - 33) * 256 + threadIdx.x;  // 64 blocks cover 16384
        if (i >= D * D) return;
        unsigned hi, lo;
        split_tf32(W_ing[i], hi, lo);
        g_wpk[i] = make_float2(__uint_as_float(hi), __uint_as_float(lo));
    }
}

// ---------------- K2: parallel bundle -------------------------------------
// blocks [0,3125):      out_ing copy + a_src (x_ing read once, 4 rows/warp)
// blocks [3125,4688):   a_dst (4 rows/warp)
// blocks [4688,4737):   zero g_cnt
#define PAR_ADST0 3125
#define PAR_ZERO0 4688
#define PAR_GRID  4737
__global__ void k_par(const float* __restrict__ x_ing, const float* __restrict__ x_taste,
                      float* __restrict__ out_ing) {
    int b = blockIdx.x;
    int lane = threadIdx.x & 31;
    int wrp  = threadIdx.x >> 5;
    if (b < PAR_ADST0) {
        int w = b * 8 + wrp;
        int row0 = w * 4;                          // exact: 25000 warps * 4 = 100000
        const float4* x4 = (const float4*)x_ing;
        float4* o4 = (float4*)out_ing;
        float4 vv = ((const float4*)g_v_src)[lane];
        float  cc = g_c_src;
        float4 xv[4];
        #pragma unroll
        for (int r = 0; r < 4; r++) xv[r] = x4[(size_t)(row0 + r) * 32 + lane];
        #pragma unroll
        for (int r = 0; r < 4; r++) {
            o4[(size_t)(row0 + r) * 32 + lane] = xv[r];
            float s = xv[r].x * vv.x + xv[r].y * vv.y + xv[r].z * vv.z + xv[r].w * vv.w;
            #pragma unroll
            for (int o = 16; o; o >>= 1) s += __shfl_down_sync(0xffffffffu, s, o);
            if (lane == 0) g_a_src[row0 + r] = s + cc;
        }
    } else if (b < PAR_ZERO0) {
        int w = (b - PAR_ADST0) * 8 + wrp;
        int row0 = w * 4;
        if (row0 >= N_TASTE) return;
        const float4* x4 = (const float4*)x_taste;
        float4 vv = ((const float4*)g_v_dst)[lane];
        float  cc = g_c_dst;
        float4 xv[4];
        #pragma unroll
        for (int r = 0; r < 4; r++) xv[r] = x4[(size_t)(row0 + r) * 32 + lane];
        #pragma unroll
        for (int r = 0; r < 4; r++) {
            float s = xv[r].x * vv.x + xv[r].y * vv.y + xv[r].z * vv.z + xv[r].w * vv.w;
            #pragma unroll
            for (int o = 16; o; o >>= 1) s += __shfl_down_sync(0xffffffffu, s, o);
            if (lane == 0) g_a_dst[row0 + r] = s + cc;
        }
    } else {
        for (int i = (b - PAR_ZERO0) * 256 + threadIdx.x; i < N_TASTE; i += 49 * 256)
            g_cnt[i] = 0;
    }
}

// ---------------- K3: fill buckets with (src, exp-weight) ------------------
__global__ void k_fill(const int* __restrict__ src, const int* __restrict__ dst) {
    int e = blockIdx.x * blockDim.x + threadIdx.x;
    if (e >= E_EDGES) return;
    int si = src[e];
    int t  = dst[e];
    float l = g_a_src[si] + g_a_dst[t];
    l = l > 0.f ? l : NEG_SLOPE * l;
    int pos = atomicAdd(&g_cnt[t], 1);          // pos < CAP w.h.p. (Poisson tail)
    g_slot[(size_t)t * CAP + pos] = make_int2(si, __float_as_int(__expf(l)));
}

// ---------------- K4: agg; 2 segments per warp, interleaved chains ---------
// warp gw owns dsts {2gw, 2gw+1}: up to 4 independent gathers in flight.
__global__ void __launch_bounds__(256) k_agg(const float* __restrict__ x_ing) {
    int lane = threadIdx.x & 31;
    int gw   = blockIdx.x * 8 + (threadIdx.x >> 5);   // 25000 warps exactly
    int t0 = gw * 2;
    int t1 = t0 + 1;
    const float4* x4 = (const float4*)x_ing;
    int n0 = g_cnt[t0];
    int n1 = g_cnt[t1];
    const int2* sp0 = g_slot + (size_t)t0 * CAP;
    const int2* sp1 = g_slot + (size_t)t1 * CAP;

    float4 acc0 = make_float4(0.f, 0.f, 0.f, 0.f);
    float4 acc1 = make_float4(0.f, 0.f, 0.f, 0.f);
    float ws0 = 0.f, ws1 = 0.f;

    int nmax = n0 > n1 ? n0 : n1;
    for (int e = 0; e < nmax; e += 2) {
        bool p00 = (e     < n0), p01 = (e + 1 < n0);
        bool p10 = (e     < n1), p11 = (e + 1 < n1);
        int2 s00 = make_int2(0, 0), s01 = make_int2(0, 0);
        int2 s10 = make_int2(0, 0), s11 = make_int2(0, 0);
        if (p00) s00 = sp0[e];
        if (p01) s01 = sp0[e + 1];
        if (p10) s10 = sp1[e];
        if (p11) s11 = sp1[e + 1];
        float w00 = p00 ? __int_as_float(s00.y) : 0.f;
        float w01 = p01 ? __int_as_float(s01.y) : 0.f;
        float w10 = p10 ? __int_as_float(s10.y) : 0.f;
        float w11 = p11 ? __int_as_float(s11.y) : 0.f;
        float4 v00 = make_float4(0.f,0.f,0.f,0.f), v01 = v00, v10 = v00, v11 = v00;
        if (p00) v00 = x4[(size_t)s00.x * 32 + lane];   // 4 independent gathers
        if (p10) v10 = x4[(size_t)s10.x * 32 + lane];
        if (p01) v01 = x4[(size_t)s01.x * 32 + lane];
        if (p11) v11 = x4[(size_t)s11.x * 32 + lane];
        ws0 += w00 + w01;
        ws1 += w10 + w11;
        acc0.x += w00*v00.x + w01*v01.x;  acc1.x += w10*v10.x + w11*v11.x;
        acc0.y += w00*v00.y + w01*v01.y;  acc1.y += w10*v10.y + w11*v11.y;
        acc0.z += w00*v00.z + w01*v01.z;  acc1.z += w10*v10.z + w11*v11.z;
        acc0.w += w00*v00.w + w01*v01.w;  acc1.w += w10*v10.w + w11*v11.w;
    }
    float i0 = 1.f / (ws0 + 1e-16f);
    float i1 = 1.f / (ws1 + 1e-16f);
    acc0.x *= i0; acc0.y *= i0; acc0.z *= i0; acc0.w *= i0;
    acc1.x *= i1; acc1.y *= i1; acc1.z *= i1; acc1.w *= i1;
    ((float4*)g_gbuf)[(size_t)t0 * 32 + lane] = acc0;
    ((float4*)g_gbuf)[(size_t)t1 * 32 + lane] = acc1;
}

// ---------------- K5: persistent TF32 3-pass MMA (W staged once/SM) --------
#define TM 128
#define SROW 132
#define N_TILES ((N_TASTE + TM - 1) / TM)     // 391
#define GEMM_BLOCKS 148
__global__ void __launch_bounds__(256) k_gemm(const float* __restrict__ bias,
                                              const float* __restrict__ x_taste,
                                              float* __restrict__ out_taste) {
    extern __shared__ float2 wpk[];     // [128][SROW] packed (hi,lo)
    int tid  = threadIdx.x;
    int lane = tid & 31;
    int wrp  = tid >> 5;

    for (int i = tid; i < D * D; i += 256) {
        int k = i >> 7, n = i & 127;
        wpk[k * SROW + n] = g_wpk[i];
    }
    __syncthreads();

    int g = lane >> 2, t4 = lane & 3;
    int rbase = wrp * 16;

    for (int tile = blockIdx.x; tile < N_TILES; tile += GEMM_BLOCKS) {
        int row0 = tile * TM;
        int r0 = row0 + rbase + g;
        int r1 = r0 + 8;
        bool v0 = r0 < N_TASTE, v1 = r1 < N_TASTE;
        const float* A0 = g_gbuf + (size_t)(v0 ? r0 : 0) * D;
        const float* A1 = g_gbuf + (size_t)(v1 ? r1 : 0) * D;

        float acc[16][4];
        #pragma unroll
        for (int nn = 0; nn < 16; nn++)
            #pragma unroll
            for (int j = 0; j < 4; j++) acc[nn][j] = 0.f;

        #pragma unroll 1
        for (int kk = 0; kk < 16; kk++) {
            int k0 = kk * 8;
            float a0f = v0 ? A0[k0 + t4    ] : 0.f;
            float a2f = v0 ? A0[k0 + t4 + 4] : 0.f;
            float a1f = v1 ? A1[k0 + t4    ] : 0.f;
            float a3f = v1 ? A1[k0 + t4 + 4] : 0.f;
            unsigned a0h,a0l,a1h,a1l,a2h,a2l,a3h,a3l;
            split_tf32(a0f, a0h, a0l);
            split_tf32(a1f, a1h, a1l);
            split_tf32(a2f, a2h, a2l);
            split_tf32(a3f, a3h, a3l);
            #pragma unroll
            for (int nn = 0; nn < 16; nn++) {
                int col = nn * 8 + g;
                float2 b0 = wpk[(k0 + t4    ) * SROW + col];   // LDS.64: (hi, lo)
                float2 b1 = wpk[(k0 + t4 + 4) * SROW + col];
                unsigned b0h = __float_as_uint(b0.x), b0l = __float_as_uint(b0.y);
                unsigned b1h = __float_as_uint(b1.x), b1l = __float_as_uint(b1.y);
                mma_tf32(acc[nn], a0h,a1h,a2h,a3h, b0h,b1h);   // hi*hi
                mma_tf32(acc[nn], a0h,a1h,a2h,a3h, b0l,b1l);   // hi*lo
                mma_tf32(acc[nn], a0l,a1l,a2l,a3l, b0h,b1h);   // lo*hi
            }
        }

        float has0 = (v0 && g_cnt[r0] > 0) ? 1.f : 0.f;
        float has1 = (v1 && g_cnt[r1] > 0) ? 1.f : 0.f;
        #pragma unroll
        for (int nn = 0; nn < 16; nn++) {
            int col = nn * 8 + 2 * t4;
            float2 bj = *(const float2*)(bias + col);
            if (v0) {
                float2 xt = *(const float2*)(x_taste + (size_t)r0 * D + col);
                float2 o;
                o.x = fmaxf(has0 * (acc[nn][0] + bj.x), 0.f) * 0.5f + 0.5f * xt.x;
                o.y = fmaxf(has0 * (acc[nn][1] + bj.y), 0.f) * 0.5f + 0.5f * xt.y;
                *(float2*)(out_taste + (size_t)r0 * D + col) = o;
            }
            if (v1) {
                float2 xt = *(const float2*)(x_taste + (size_t)r1 * D + col);
                float2 o;
                o.x = fmaxf(has1 * (acc[nn][2] + bj.x), 0.f) * 0.5f + 0.5f * xt.x;
                o.y = fmaxf(has1 * (acc[nn][3] + bj.y), 0.f) * 0.5f + 0.5f * xt.y;
                *(float2*)(out_taste + (size_t)r1 * D + col) = o;
            }
        }
    }
}

// ---------------- launcher: single stream, 5 kernels, 0 events -------------
extern "C" void kernel_launch(void* const* d_in, const int* in_sizes, int n_in,
                              void* d_out, int out_size) {
    const float* x_ing   = (const float*)d_in[0];
    const float* x_taste = (const float*)d_in[1];
    const float* W_ing   = (const float*)d_in[2];
    const float* b_ing   = (const float*)d_in[3];
    const float* W_taste = (const float*)d_in[4];
    const float* b_taste = (const float*)d_in[5];
    const float* att_src = (const float*)d_in[6];
    const float* att_dst = (const float*)d_in[7];
    // d_in[8..10] (Wk, bk, q): softmax over single metapath == 1.0 -> dead code
    const int* src_idx = (const int*)d_in[11];
    const int* dst_idx = (const int*)d_in[12];

    float* out       = (float*)d_out;
    float* out_ing   = out;                      // [N_ING, D] == x_ing
    float* out_taste = out + (size_t)N_ING * D;  // [N_TASTE, D]

    static const int SMEM_GEMM = D * SROW * (int)sizeof(float2);  // 135168
    static bool init = false;
    if (!init) {
        init = true;
        cudaFuncSetAttribute(k_gemm, cudaFuncAttributeMaxDynamicSharedMemorySize, SMEM_GEMM);
    }

    k_prep<<<97, 256>>>(W_ing, b_ing, W_taste, b_taste, att_src, att_dst);
    k_par<<<PAR_GRID, 256>>>(x_ing, x_taste, out_ing);
    k_fill<<<(E_EDGES + 255) / 256, 256>>>(src_idx, dst_idx);
    k_agg<<<3125, 256>>>(x_ing);                 // 25000 warps, 2 dsts each
    k_gemm<<<GEMM_BLOCKS, 256, SMEM_GEMM>>>(b_ing, x_taste, out_taste);
}